// round 1
// baseline (speedup 1.0000x reference)
#include <cuda_runtime.h>
#include <math.h>

// Problem constants
#define M1   16384     // B*T*HW rows
#define CDIM 512
#define N1   1536      // 3*C
#define NH   8
#define HD   64
#define TT   16
#define HWDIM 1024
#define NPROB 128      // NH * TT

// Scratch (allocation-free rule: __device__ globals)
__device__ float g_q[(size_t)NPROB * HWDIM * HD];   // [p][hw][d], p = h*16+t
__device__ float g_k[(size_t)NPROB * HWDIM * HD];
__device__ float g_v[(size_t)NPROB * HWDIM * HD];
__device__ float g_att[(size_t)M1 * CDIM];          // flat (h,q,t,d) == row-major (16384,512)

// ---------------------------------------------------------------------------
// Register-blocked SGEMM: C = A(MxK) @ B(KxN) + bias
// BM=BN=128, BK=16, 256 threads, 8x8 per thread.
// EPI==1: scatter into g_q/g_k/g_v (QKV projection)
// EPI==2: Cout[m*N+n] = acc + bias[n]
// All dims are multiples of tile sizes for this problem (no bounds checks).
// ---------------------------------------------------------------------------
template <int EPI>
__global__ __launch_bounds__(256) void sgemm_kernel(
    const float* __restrict__ A, const float* __restrict__ B,
    const float* __restrict__ bias, float* __restrict__ Cout,
    int M, int N, int K)
{
    __shared__ float As[16 * 128];   // transposed: As[k][m]
    __shared__ float Bs[16 * 128];   // Bs[k][n]

    const int tid = threadIdx.x;
    const int m0  = blockIdx.y * 128;
    const int n0  = blockIdx.x * 128;
    const int ty  = tid >> 4;        // 0..15
    const int tx  = tid & 15;        // 0..15

    float acc[8][8];
#pragma unroll
    for (int i = 0; i < 8; ++i)
#pragma unroll
        for (int j = 0; j < 8; ++j) acc[i][j] = 0.0f;

    for (int k0 = 0; k0 < K; k0 += 16) {
#pragma unroll
        for (int i = 0; i < 2; ++i) {
            int idx = i * 256 + tid;            // 0..511 float4 slots
            // A tile: 128 rows x 16 cols = 512 float4 (4 per row)
            int ar = idx >> 2, ac = (idx & 3) << 2;
            float4 va = *(const float4*)(A + (size_t)(m0 + ar) * K + k0 + ac);
            As[(ac + 0) * 128 + ar] = va.x;
            As[(ac + 1) * 128 + ar] = va.y;
            As[(ac + 2) * 128 + ar] = va.z;
            As[(ac + 3) * 128 + ar] = va.w;
            // B tile: 16 rows x 128 cols = 512 float4 (32 per row)
            int br = idx >> 5, bc = (idx & 31) << 2;
            float4 vb = *(const float4*)(B + (size_t)(k0 + br) * N + n0 + bc);
            *(float4*)(Bs + br * 128 + bc) = vb;
        }
        __syncthreads();

#pragma unroll
        for (int kk = 0; kk < 16; ++kk) {
            float ra[8], rb[8];
            *(float4*)(ra)     = *(const float4*)(As + kk * 128 + ty * 8);
            *(float4*)(ra + 4) = *(const float4*)(As + kk * 128 + ty * 8 + 4);
            *(float4*)(rb)     = *(const float4*)(Bs + kk * 128 + tx * 8);
            *(float4*)(rb + 4) = *(const float4*)(Bs + kk * 128 + tx * 8 + 4);
#pragma unroll
            for (int i = 0; i < 8; ++i)
#pragma unroll
                for (int j = 0; j < 8; ++j)
                    acc[i][j] += ra[i] * rb[j];
        }
        __syncthreads();
    }

    if (EPI == 1) {
        // QKV scatter: n = s*512 + h*64 + d ; m = t*1024 + hw
        // dst[s][((h*16+t)*1024 + hw)*64 + d]
#pragma unroll
        for (int i = 0; i < 8; ++i) {
            int m  = m0 + ty * 8 + i;
            int t  = m >> 10;
            int hw = m & 1023;
#pragma unroll
            for (int j = 0; j < 8; ++j) {
                int n = n0 + tx * 8 + j;
                float v = acc[i][j] + bias[n];
                int s   = n >> 9;
                int rem = n & 511;
                int h   = rem >> 6;
                int d   = rem & 63;
                int di  = ((h * 16 + t) * 1024 + hw) * 64 + d;
                float* dst = (s == 0) ? g_q : ((s == 1) ? g_k : g_v);
                dst[di] = v;
            }
        }
    } else {
#pragma unroll
        for (int i = 0; i < 8; ++i) {
            int m = m0 + ty * 8 + i;
#pragma unroll
            for (int j = 0; j < 8; ++j) {
                int n = n0 + tx * 8 + j;
                Cout[(size_t)m * N + n] = acc[i][j] + bias[n];
            }
        }
    }
}

// ---------------------------------------------------------------------------
// Attention kernel. One block = (problem p, 16-row q tile).
// Full score rows (16 x 1024) kept in smem; two-pass softmax.
// Output written with the reference's permuted reshape folded in:
//   g_att flat index = ((h*1024 + q)*16 + t)*64 + d
// ---------------------------------------------------------------------------
#define KSTRIDE 65   // padded row stride for K/V tile (conflict-free column reads)

__global__ __launch_bounds__(256) void attn_kernel()
{
    extern __shared__ float sm[];
    float* sQ   = sm;                       // 16*64   = 1024
    float* sK   = sm + 1024;                // 128*65  = 8320 (K tile, then V tile)
    float* sS   = sm + 1024 + 8320;         // 16*1024 = 16384
    float* sSum = sS + 16 * 1024;           // 16

    const int p  = blockIdx.y;              // problem: h = p>>4, t = p&15
    const int q0 = blockIdx.x * 16;
    const float* Qg = g_q + (size_t)p * HWDIM * HD;
    const float* Kg = g_k + (size_t)p * HWDIM * HD;
    const float* Vg = g_v + (size_t)p * HWDIM * HD;

    const int tid = threadIdx.x;
    const int a   = tid >> 5;               // warp id 0..7
    const int j   = tid & 31;               // lane

    // Load Q tile: 16x64 = 256 float4, one per thread
    {
        int r = tid >> 4;
        int c = (tid & 15) << 2;
        *(float4*)(sQ + r * 64 + c) =
            *(const float4*)(Qg + (size_t)(q0 + r) * HD + c);
    }

    // ---- Phase 1: scores S = Q @ K^T / 8, tiles of 128 K-rows ----
    for (int kt = 0; kt < 8; ++kt) {
        __syncthreads();   // previous tile fully consumed
        // load K tile 128x64 -> sK (padded), 2048 float4 / 256 thr = 8 each
#pragma unroll
        for (int i = 0; i < 8; ++i) {
            int idx = i * 256 + tid;
            int r = idx >> 4;
            int c = (idx & 15) << 2;
            float4 v = *(const float4*)(Kg + (size_t)(kt * 128 + r) * HD + c);
            float* d = sK + r * KSTRIDE + c;
            d[0] = v.x; d[1] = v.y; d[2] = v.z; d[3] = v.w;
        }
        __syncthreads();

        float s00 = 0, s01 = 0, s02 = 0, s03 = 0;
        float s10 = 0, s11 = 0, s12 = 0, s13 = 0;
        const float* qa = sQ + a * 64;        // row a
        const float* qb = sQ + (a + 8) * 64;  // row a+8
#pragma unroll
        for (int c = 0; c < 64; ++c) {
            float va = qa[c];
            float vb = qb[c];
            float k0v = sK[(j)      * KSTRIDE + c];
            float k1v = sK[(j + 32) * KSTRIDE + c];
            float k2v = sK[(j + 64) * KSTRIDE + c];
            float k3v = sK[(j + 96) * KSTRIDE + c];
            s00 += va * k0v; s01 += va * k1v; s02 += va * k2v; s03 += va * k3v;
            s10 += vb * k0v; s11 += vb * k1v; s12 += vb * k2v; s13 += vb * k3v;
        }
        int b0 = a * 1024 + kt * 128 + j;
        int b1 = (a + 8) * 1024 + kt * 128 + j;
        sS[b0]      = s00 * 0.125f;
        sS[b0 + 32] = s01 * 0.125f;
        sS[b0 + 64] = s02 * 0.125f;
        sS[b0 + 96] = s03 * 0.125f;
        sS[b1]      = s10 * 0.125f;
        sS[b1 + 32] = s11 * 0.125f;
        sS[b1 + 64] = s12 * 0.125f;
        sS[b1 + 96] = s13 * 0.125f;
    }
    __syncthreads();

    // ---- Phase 2: softmax over each of 16 rows (warp w -> rows w, w+8) ----
#pragma unroll
    for (int rr = 0; rr < 2; ++rr) {
        int r = a + rr * 8;
        float* row = sS + r * 1024;
        float mx = -1e30f;
        for (int i = j; i < 1024; i += 32) mx = fmaxf(mx, row[i]);
#pragma unroll
        for (int o = 16; o > 0; o >>= 1) mx = fmaxf(mx, __shfl_xor_sync(0xFFFFFFFFu, mx, o));
        float sum = 0.0f;
        for (int i = j; i < 1024; i += 32) {
            float e = __expf(row[i] - mx);
            row[i] = e;
            sum += e;
        }
#pragma unroll
        for (int o = 16; o > 0; o >>= 1) sum += __shfl_xor_sync(0xFFFFFFFFu, sum, o);
        if (j == 0) sSum[r] = sum;
    }
    __syncthreads();

    // ---- Phase 3: out = P @ V (16x64 over K=1024), V tiles of 128 rows ----
    float o00 = 0, o01 = 0, o10 = 0, o11 = 0;   // rows {a, a+8} x cols {j, j+32}
    for (int vt = 0; vt < 8; ++vt) {
        __syncthreads();   // previous V tile consumed (first iter: guards sK reuse)
#pragma unroll
        for (int i = 0; i < 8; ++i) {
            int idx = i * 256 + tid;
            int r = idx >> 4;
            int c = (idx & 15) << 2;
            float4 v = *(const float4*)(Vg + (size_t)(vt * 128 + r) * HD + c);
            float* d = sK + r * KSTRIDE + c;
            d[0] = v.x; d[1] = v.y; d[2] = v.z; d[3] = v.w;
        }
        __syncthreads();

        const float* p0 = sS + a * 1024 + vt * 128;
        const float* p1 = sS + (a + 8) * 1024 + vt * 128;
#pragma unroll 8
        for (int kk = 0; kk < 128; ++kk) {
            float v0 = sK[kk * KSTRIDE + j];
            float v1 = sK[kk * KSTRIDE + j + 32];
            float x0 = p0[kk];
            float x1 = p1[kk];
            o00 += x0 * v0; o01 += x0 * v1;
            o10 += x1 * v0; o11 += x1 * v1;
        }
    }

    float inv0 = 1.0f / sSum[a];
    float inv1 = 1.0f / sSum[a + 8];
    const int h = p >> 4;
    const int t = p & 15;
    // permuted reshape folded in: flat (h, q, t, d)
    size_t base0 = ((size_t)(h * 1024 + q0 + a)     * 16 + t) * 64;
    size_t base1 = ((size_t)(h * 1024 + q0 + a + 8) * 16 + t) * 64;
    g_att[base0 + j]      = o00 * inv0;
    g_att[base0 + j + 32] = o01 * inv0;
    g_att[base1 + j]      = o10 * inv1;
    g_att[base1 + j + 32] = o11 * inv1;
}

// ---------------------------------------------------------------------------
extern "C" void kernel_launch(void* const* d_in, const int* in_sizes, int n_in,
                              void* d_out, int out_size)
{
    const float* x    = (const float*)d_in[0];
    const float* Wqkv = (const float*)d_in[1];
    const float* bqkv = (const float*)d_in[2];
    const float* Wout = (const float*)d_in[3];
    const float* bout = (const float*)d_in[4];
    float* out = (float*)d_out;

    // 1) QKV projection + scatter to per-(h,t) contiguous Q/K/V
    sgemm_kernel<1><<<dim3(N1 / 128, M1 / 128), 256>>>(
        x, Wqkv, bqkv, nullptr, M1, N1, CDIM);

    // 2) attention (128 problems x 64 q-tiles)
    const int attn_smem = (1024 + 128 * KSTRIDE + 16 * 1024 + 16) * (int)sizeof(float);
    cudaFuncSetAttribute(attn_kernel,
                         cudaFuncAttributeMaxDynamicSharedMemorySize, attn_smem);
    attn_kernel<<<dim3(HWDIM / 16, NPROB), 256, attn_smem>>>();

    // 3) output projection: g_att(16384x512) @ Wout(512x512) + bout
    float* gatt_ptr = nullptr;
    cudaGetSymbolAddress((void**)&gatt_ptr, g_att);
    sgemm_kernel<2><<<dim3(CDIM / 128, M1 / 128), 256>>>(
        gatt_ptr, Wout, bout, out, M1, CDIM, CDIM);
}

// round 3
// speedup vs baseline: 4.0965x; 4.0965x over previous
#include <cuda_runtime.h>
#include <math.h>

// Problem constants
#define M1    16384     // B*T*HW rows
#define CDIM  512
#define N1    1536      // 3*C
#define NH    8
#define HD    64
#define TT    16
#define HWDIM 1024
#define NPROB 128       // NH * TT

// Scratch (allocation-free rule: __device__ globals)
__device__ float g_q[(size_t)NPROB * HWDIM * HD];   // [p][hw][d], p = h*16+t  (pre-scaled by 1/8, tf32-rounded)
__device__ float g_k[(size_t)NPROB * HWDIM * HD];
__device__ float g_v[(size_t)NPROB * HWDIM * HD];
__device__ float g_att[(size_t)M1 * CDIM];          // flat (h,q,t,d) == row-major (16384,512)

// ---------------------------------------------------------------------------
// helpers
// ---------------------------------------------------------------------------
__device__ __forceinline__ float to_tf32(float x) {
    unsigned r;
    asm("cvt.rna.tf32.f32 %0, %1;" : "=r"(r) : "f"(x));
    return __uint_as_float(r);
}

__device__ __forceinline__ void mma8(float c[4],
                                     float a0, float a1, float a2, float a3,
                                     float b0, float b1) {
    asm volatile(
        "mma.sync.aligned.m16n8k8.row.col.f32.tf32.tf32.f32 "
        "{%0,%1,%2,%3}, {%4,%5,%6,%7}, {%8,%9}, {%0,%1,%2,%3};\n"
        : "+f"(c[0]), "+f"(c[1]), "+f"(c[2]), "+f"(c[3])
        : "r"(__float_as_uint(a0)), "r"(__float_as_uint(a1)),
          "r"(__float_as_uint(a2)), "r"(__float_as_uint(a3)),
          "r"(__float_as_uint(b0)), "r"(__float_as_uint(b1)));
}

// ---------------------------------------------------------------------------
// TF32 tensor-core GEMM: C = A(MxK) @ B(KxN) + bias
// BM=BN=128, BK=32, 256 threads; warp grid 2(m)x4(n), warp tile 64x32.
// EPI==1: scatter into g_q/g_k/g_v (QKV projection), Q pre-scaled by 1/8.
// EPI==2: Cout[m*N+n] = acc + bias[n]
// ---------------------------------------------------------------------------
#define GST 132   // smem row stride (== 4 mod 32 -> conflict-free fragment lds)

template <int EPI>
__global__ __launch_bounds__(256) void sgemm_tc(
    const float* __restrict__ A, const float* __restrict__ B,
    const float* __restrict__ bias, float* __restrict__ Cout,
    int M, int N, int K)
{
    __shared__ float As[32 * GST];   // As[k][m]
    __shared__ float Bs[32 * GST];   // Bs[k][n]

    const int tid  = threadIdx.x;
    const int warp = tid >> 5;
    const int lane = tid & 31;
    const int g    = lane >> 2;      // 0..7
    const int tg   = lane & 3;       // 0..3
    const int wm   = warp & 1;       // 0..1  (64 rows each)
    const int wn   = warp >> 1;      // 0..3  (32 cols each)
    const int m0   = blockIdx.y * 128;
    const int n0   = blockIdx.x * 128;

    float acc[4][4][4];
#pragma unroll
    for (int i = 0; i < 4; ++i)
#pragma unroll
        for (int j = 0; j < 4; ++j)
#pragma unroll
            for (int r = 0; r < 4; ++r) acc[i][j][r] = 0.0f;

    for (int k0 = 0; k0 < K; k0 += 32) {
        // load A tile 128x32 (transposed into As[k][m]), tf32-rounded
#pragma unroll
        for (int i = 0; i < 4; ++i) {
            int idx = i * 256 + tid;          // 1024 float4 slots
            int ar = idx >> 3, ac = (idx & 7) << 2;
            float4 v = *(const float4*)(A + (size_t)(m0 + ar) * K + k0 + ac);
            As[(ac + 0) * GST + ar] = to_tf32(v.x);
            As[(ac + 1) * GST + ar] = to_tf32(v.y);
            As[(ac + 2) * GST + ar] = to_tf32(v.z);
            As[(ac + 3) * GST + ar] = to_tf32(v.w);
        }
        // load B tile 32x128 into Bs[k][n]
#pragma unroll
        for (int i = 0; i < 4; ++i) {
            int idx = i * 256 + tid;
            int br = idx >> 5, bc = (idx & 31) << 2;
            float4 v = *(const float4*)(B + (size_t)(k0 + br) * N + n0 + bc);
            float4 w;
            w.x = to_tf32(v.x); w.y = to_tf32(v.y);
            w.z = to_tf32(v.z); w.w = to_tf32(v.w);
            *(float4*)(Bs + br * GST + bc) = w;
        }
        __syncthreads();

#pragma unroll
        for (int ks = 0; ks < 4; ++ks) {
            int kk = ks * 8;
            float a[4][4], b[4][2];
#pragma unroll
            for (int mt = 0; mt < 4; ++mt) {
                int m = wm * 64 + mt * 16 + g;
                a[mt][0] = As[(kk + tg)     * GST + m];
                a[mt][1] = As[(kk + tg)     * GST + m + 8];
                a[mt][2] = As[(kk + tg + 4) * GST + m];
                a[mt][3] = As[(kk + tg + 4) * GST + m + 8];
            }
#pragma unroll
            for (int nt = 0; nt < 4; ++nt) {
                int n = wn * 32 + nt * 8 + g;
                b[nt][0] = Bs[(kk + tg)     * GST + n];
                b[nt][1] = Bs[(kk + tg + 4) * GST + n];
            }
#pragma unroll
            for (int mt = 0; mt < 4; ++mt)
#pragma unroll
                for (int nt = 0; nt < 4; ++nt)
                    mma8(acc[mt][nt], a[mt][0], a[mt][1], a[mt][2], a[mt][3],
                         b[nt][0], b[nt][1]);
        }
        __syncthreads();
    }

    // ---- epilogue ----
    if (EPI == 1) {
        // n = s*512 + h*64 + d ; m = t*1024 + hw
        // dst[s][((h*16+t)*1024 + hw)*64 + d] ; Q additionally scaled by 1/8
#pragma unroll
        for (int mt = 0; mt < 4; ++mt) {
            int m  = m0 + wm * 64 + mt * 16 + g;
            int t  = m >> 10;
            int hw0 = m & 1023;
            int hw1 = (m + 8) & 1023;
#pragma unroll
            for (int nt = 0; nt < 4; ++nt) {
                int n   = n0 + wn * 32 + nt * 8 + 2 * tg;
                float2 bv = *(const float2*)(bias + n);
                int s   = n >> 9;
                int rem = n & 511;
                int h   = rem >> 6;
                int d   = rem & 63;
                float* dst = (s == 0) ? g_q : ((s == 1) ? g_k : g_v);
                float sc = (s == 0) ? 0.125f : 1.0f;
                size_t base = ((size_t)(h * 16 + t) * 1024) * 64 + d;
                float2 v0, v1;
                v0.x = to_tf32((acc[mt][nt][0] + bv.x) * sc);
                v0.y = to_tf32((acc[mt][nt][1] + bv.y) * sc);
                v1.x = to_tf32((acc[mt][nt][2] + bv.x) * sc);
                v1.y = to_tf32((acc[mt][nt][3] + bv.y) * sc);
                *(float2*)(dst + base + (size_t)hw0 * 64) = v0;
                *(float2*)(dst + base + (size_t)hw1 * 64) = v1;
            }
        }
    } else {
#pragma unroll
        for (int mt = 0; mt < 4; ++mt) {
            int m = m0 + wm * 64 + mt * 16 + g;
#pragma unroll
            for (int nt = 0; nt < 4; ++nt) {
                int n = n0 + wn * 32 + nt * 8 + 2 * tg;
                float2 bv = *(const float2*)(bias + n);
                float2 v0, v1;
                v0.x = acc[mt][nt][0] + bv.x;
                v0.y = acc[mt][nt][1] + bv.y;
                v1.x = acc[mt][nt][2] + bv.x;
                v1.y = acc[mt][nt][3] + bv.y;
                *(float2*)(Cout + (size_t)m * N + n)       = v0;
                *(float2*)(Cout + (size_t)(m + 8) * N + n) = v1;
            }
        }
    }
}

// ---------------------------------------------------------------------------
// Flash attention (TF32 mma). Block = (problem p, 128-row q tile), 4 warps.
// Warp w owns q rows [w*32, w*32+32). K iterated in 64-key tiles with online
// softmax. P goes through per-warp smem for the C->A fragment relayout.
// Output written with the reference's permuted reshape folded in.
// ---------------------------------------------------------------------------
#define AST 68   // smem row stride for attention tiles (== 4 mod 32)

__global__ __launch_bounds__(128) void attn_kernel()
{
    extern __shared__ float sm[];
    float* Qs = sm;                      // 128 x AST
    float* Ks = Qs + 128 * AST;          // 64 x AST
    float* Vs = Ks + 64 * AST;           // 64 x AST
    float* Ps = Vs + 64 * AST;           // 128 x AST (warp w -> rows w*32..)

    const int p  = blockIdx.y;           // h = p>>4, t = p&15
    const int q0 = blockIdx.x * 128;
    const float* Qg = g_q + (size_t)p * HWDIM * HD;
    const float* Kg = g_k + (size_t)p * HWDIM * HD;
    const float* Vg = g_v + (size_t)p * HWDIM * HD;

    const int tid  = threadIdx.x;
    const int w    = tid >> 5;
    const int lane = tid & 31;
    const int g    = lane >> 2;
    const int tg   = lane & 3;
    const int qb   = w * 32;

    // load Q tile 128x64 (already tf32 + 1/8-scaled at QKV epilogue)
#pragma unroll
    for (int i = 0; i < 16; ++i) {
        int idx = i * 128 + tid;
        int r = idx >> 4, c = (idx & 15) << 2;
        *(float4*)(Qs + r * AST + c) =
            *(const float4*)(Qg + (size_t)(q0 + r) * HD + c);
    }

    float O[2][8][4];
#pragma unroll
    for (int mt = 0; mt < 2; ++mt)
#pragma unroll
        for (int nt = 0; nt < 8; ++nt)
#pragma unroll
            for (int r = 0; r < 4; ++r) O[mt][nt][r] = 0.0f;
    float mo[4] = {-1e30f, -1e30f, -1e30f, -1e30f};
    float l[4]  = {0.0f, 0.0f, 0.0f, 0.0f};

    for (int kt = 0; kt < 16; ++kt) {
        __syncthreads();
        // load K,V 64x64 tiles (already tf32)
#pragma unroll
        for (int i = 0; i < 8; ++i) {
            int idx = i * 128 + tid;
            int r = idx >> 4, c = (idx & 15) << 2;
            size_t go = (size_t)(kt * 64 + r) * HD + c;
            *(float4*)(Ks + r * AST + c) = *(const float4*)(Kg + go);
            *(float4*)(Vs + r * AST + c) = *(const float4*)(Vg + go);
        }
        __syncthreads();

        // ---- S = Q K^T (pre-scaled by 1/8 via Q) ----
        float S[2][8][4];
#pragma unroll
        for (int mt = 0; mt < 2; ++mt)
#pragma unroll
            for (int nk = 0; nk < 8; ++nk)
#pragma unroll
                for (int r = 0; r < 4; ++r) S[mt][nk][r] = 0.0f;

#pragma unroll
        for (int kd = 0; kd < 8; ++kd) {
            int kk = kd * 8;
            float a[2][4], b[8][2];
#pragma unroll
            for (int mt = 0; mt < 2; ++mt) {
                int m = qb + mt * 16 + g;
                a[mt][0] = Qs[m * AST + kk + tg];
                a[mt][1] = Qs[(m + 8) * AST + kk + tg];
                a[mt][2] = Qs[m * AST + kk + tg + 4];
                a[mt][3] = Qs[(m + 8) * AST + kk + tg + 4];
            }
#pragma unroll
            for (int nk = 0; nk < 8; ++nk) {
                int key = nk * 8 + g;
                b[nk][0] = Ks[key * AST + kk + tg];
                b[nk][1] = Ks[key * AST + kk + tg + 4];
            }
#pragma unroll
            for (int mt = 0; mt < 2; ++mt)
#pragma unroll
                for (int nk = 0; nk < 8; ++nk)
                    mma8(S[mt][nk], a[mt][0], a[mt][1], a[mt][2], a[mt][3],
                         b[nk][0], b[nk][1]);
        }

        // ---- online softmax ----
        float mn[4];
#pragma unroll
        for (int mt = 0; mt < 2; ++mt) {
            float h0 = -1e30f, h1 = -1e30f;
#pragma unroll
            for (int nk = 0; nk < 8; ++nk) {
                h0 = fmaxf(h0, fmaxf(S[mt][nk][0], S[mt][nk][1]));
                h1 = fmaxf(h1, fmaxf(S[mt][nk][2], S[mt][nk][3]));
            }
            mn[2 * mt] = h0; mn[2 * mt + 1] = h1;
        }
#pragma unroll
        for (int s = 0; s < 4; ++s) {
            mn[s] = fmaxf(mn[s], __shfl_xor_sync(0xFFFFFFFFu, mn[s], 1));
            mn[s] = fmaxf(mn[s], __shfl_xor_sync(0xFFFFFFFFu, mn[s], 2));
            mn[s] = fmaxf(mn[s], mo[s]);
        }
        float al[4];
#pragma unroll
        for (int s = 0; s < 4; ++s) al[s] = __expf(mo[s] - mn[s]);
        // rescale O
#pragma unroll
        for (int mt = 0; mt < 2; ++mt)
#pragma unroll
            for (int nt = 0; nt < 8; ++nt) {
                O[mt][nt][0] *= al[2 * mt];     O[mt][nt][1] *= al[2 * mt];
                O[mt][nt][2] *= al[2 * mt + 1]; O[mt][nt][3] *= al[2 * mt + 1];
            }
        // P = exp(S - mn), partial row sums, P -> smem (tf32)
        float rs[4] = {0, 0, 0, 0};
        __syncwarp();
#pragma unroll
        for (int mt = 0; mt < 2; ++mt) {
            int r0 = qb + mt * 16 + g;
#pragma unroll
            for (int nk = 0; nk < 8; ++nk) {
                float p0 = __expf(S[mt][nk][0] - mn[2 * mt]);
                float p1 = __expf(S[mt][nk][1] - mn[2 * mt]);
                float p2 = __expf(S[mt][nk][2] - mn[2 * mt + 1]);
                float p3 = __expf(S[mt][nk][3] - mn[2 * mt + 1]);
                rs[2 * mt]     += p0 + p1;
                rs[2 * mt + 1] += p2 + p3;
                float2 u0, u1;
                u0.x = to_tf32(p0); u0.y = to_tf32(p1);
                u1.x = to_tf32(p2); u1.y = to_tf32(p3);
                *(float2*)(Ps + r0 * AST + nk * 8 + 2 * tg)       = u0;
                *(float2*)(Ps + (r0 + 8) * AST + nk * 8 + 2 * tg) = u1;
            }
        }
        __syncwarp();
#pragma unroll
        for (int s = 0; s < 4; ++s) {
            rs[s] += __shfl_xor_sync(0xFFFFFFFFu, rs[s], 1);
            rs[s] += __shfl_xor_sync(0xFFFFFFFFu, rs[s], 2);
            l[s] = l[s] * al[s] + rs[s];
            mo[s] = mn[s];
        }

        // ---- O += P V ----
#pragma unroll
        for (int ks = 0; ks < 8; ++ks) {
            int kk = ks * 8;
            float a[2][4], b[8][2];
#pragma unroll
            for (int mt = 0; mt < 2; ++mt) {
                int r0 = qb + mt * 16 + g;
                a[mt][0] = Ps[r0 * AST + kk + tg];
                a[mt][1] = Ps[(r0 + 8) * AST + kk + tg];
                a[mt][2] = Ps[r0 * AST + kk + tg + 4];
                a[mt][3] = Ps[(r0 + 8) * AST + kk + tg + 4];
            }
#pragma unroll
            for (int nt = 0; nt < 8; ++nt) {
                int d = nt * 8 + g;
                b[nt][0] = Vs[(kk + tg) * AST + d];
                b[nt][1] = Vs[(kk + tg + 4) * AST + d];
            }
#pragma unroll
            for (int mt = 0; mt < 2; ++mt)
#pragma unroll
                for (int nt = 0; nt < 8; ++nt)
                    mma8(O[mt][nt], a[mt][0], a[mt][1], a[mt][2], a[mt][3],
                         b[nt][0], b[nt][1]);
        }
    }

    // ---- epilogue: normalize + permuted store ----
    const int h = p >> 4;
    const int t = p & 15;
#pragma unroll
    for (int mt = 0; mt < 2; ++mt) {
        int row = qb + mt * 16 + g;
        int q   = q0 + row;
        float inv0 = 1.0f / l[2 * mt];
        float inv1 = 1.0f / l[2 * mt + 1];
        size_t base0 = ((size_t)(h * 1024 + q) * 16 + t) * 64;
        size_t base1 = ((size_t)(h * 1024 + q + 8) * 16 + t) * 64;
#pragma unroll
        for (int nt = 0; nt < 8; ++nt) {
            int d = nt * 8 + 2 * tg;
            float2 v0, v1;
            v0.x = O[mt][nt][0] * inv0; v0.y = O[mt][nt][1] * inv0;
            v1.x = O[mt][nt][2] * inv1; v1.y = O[mt][nt][3] * inv1;
            *(float2*)(g_att + base0 + d) = v0;
            *(float2*)(g_att + base1 + d) = v1;
        }
    }
}

// ---------------------------------------------------------------------------
extern "C" void kernel_launch(void* const* d_in, const int* in_sizes, int n_in,
                              void* d_out, int out_size)
{
    const float* x    = (const float*)d_in[0];
    const float* Wqkv = (const float*)d_in[1];
    const float* bqkv = (const float*)d_in[2];
    const float* Wout = (const float*)d_in[3];
    const float* bout = (const float*)d_in[4];
    float* out = (float*)d_out;

    // 1) QKV projection (TF32 TC) + scatter to per-(h,t) contiguous Q/K/V
    sgemm_tc<1><<<dim3(N1 / 128, M1 / 128), 256>>>(
        x, Wqkv, bqkv, nullptr, M1, N1, CDIM);

    // 2) flash attention (128 problems x 8 q-tiles of 128)
    const int attn_smem = (128 + 64 + 64 + 128) * AST * (int)sizeof(float);
    cudaFuncSetAttribute(attn_kernel,
                         cudaFuncAttributeMaxDynamicSharedMemorySize, attn_smem);
    attn_kernel<<<dim3(HWDIM / 128, NPROB), 128, attn_smem>>>();

    // 3) output projection: g_att(16384x512) @ Wout(512x512) + bout
    float* gatt_ptr = nullptr;
    cudaGetSymbolAddress((void**)&gatt_ptr, g_att);
    sgemm_tc<2><<<dim3(CDIM / 128, M1 / 128), 256>>>(
        gatt_ptr, Wout, bout, out, M1, CDIM, CDIM);
}